// round 16
// baseline (speedup 1.0000x reference)
#include <cuda_runtime.h>
#include <math.h>

#define S_SCENES 128
#define N_PED    64
#define HID      128
#define TOTAL    (S_SCENES * N_PED)   // 8192
#define QSCALE   0.17677669529663687f // 1/sqrt(32)

// ---------------- device scratch ----------------
__device__ float g_y[TOTAL * 384];    // q | kf | vf  (q pre-scaled)
__device__ float g_wk2[HID * 64];     // Wk @ W2
__device__ float g_wv2[HID * 64];     // Wv @ W2
__device__ float g_wco[HID * HID];    // P2 @ out_w
__device__ float g_bco[HID];          // proj_b + P2 @ out_b

// ---------------- f32x2 helpers ----------------
__device__ __forceinline__ unsigned long long dup2(float x) {
    unsigned long long r;
    asm("mov.b64 %0, {%1, %1};" : "=l"(r) : "r"(__float_as_uint(x)));
    return r;
}
__device__ __forceinline__ unsigned long long pk2(float lo, float hi) {
    unsigned long long r;
    asm("mov.b64 %0, {%1, %2};" : "=l"(r) : "r"(__float_as_uint(lo)), "r"(__float_as_uint(hi)));
    return r;
}
__device__ __forceinline__ void ffma2(unsigned long long& d,
                                      unsigned long long a, unsigned long long b) {
    asm("fma.rn.f32x2 %0, %1, %2, %0;" : "+l"(d) : "l"(a), "l"(b));
}
__device__ __forceinline__ float2 unpk2(unsigned long long v) {
    unsigned lo, hi;
    asm("mov.b64 {%0, %1}, %2;" : "=r"(lo), "=r"(hi) : "l"(v));
    return make_float2(__uint_as_float(lo), __uint_as_float(hi));
}
union F4U { float4 f4; unsigned long long u[2]; float f[4]; };

// ---------------- dot helpers (prep) ----------------
__device__ __forceinline__ float dot32_col(const float* __restrict__ row,
                                           const float* __restrict__ colbase,
                                           int ldc, int c, int d0) {
    float a0 = 0.f, a1 = 0.f, a2 = 0.f, a3 = 0.f;
    #pragma unroll
    for (int dd = 0; dd < 32; dd += 4) {
        int d = d0 + dd;
        float4 wv = *(const float4*)&row[d];
        a0 = fmaf(wv.x, colbase[(d + 0) * ldc + c], a0);
        a1 = fmaf(wv.y, colbase[(d + 1) * ldc + c], a1);
        a2 = fmaf(wv.z, colbase[(d + 2) * ldc + c], a2);
        a3 = fmaf(wv.w, colbase[(d + 3) * ldc + c], a3);
    }
    return (a0 + a1) + (a2 + a3);
}
__device__ __forceinline__ float dot32_vec(const float* __restrict__ a,
                                           const float* __restrict__ b, int d0) {
    float a0 = 0.f, a1 = 0.f, a2 = 0.f, a3 = 0.f;
    #pragma unroll
    for (int dd = 0; dd < 32; dd += 4) {
        int d = d0 + dd;
        float4 av = *(const float4*)&a[d];
        float4 bv = *(const float4*)&b[d];
        a0 = fmaf(av.x, bv.x, a0);
        a1 = fmaf(av.y, bv.y, a1);
        a2 = fmaf(av.z, bv.z, a2);
        a3 = fmaf(av.w, bv.w, a3);
    }
    return (a0 + a1) + (a2 + a3);
}

// ---------------- Combined G1 + prep kernel (R15 proven) ----------------
#define AS_P 132
#define BS_P 68
#define QKV_BLOCKS 384

__global__ void __launch_bounds__(256) qkv_prep(const float* __restrict__ X,
                                                const float* __restrict__ ipw,
                                                const float* __restrict__ ipb,
                                                const float* __restrict__ W2,
                                                const float* __restrict__ b2,
                                                const float* __restrict__ outw,
                                                const float* __restrict__ outb,
                                                const float* __restrict__ pw,
                                                const float* __restrict__ pb)
{
    int bid = blockIdx.x;
    int tid = threadIdx.x;

    if (bid >= QKV_BLOCKS) {
        int g = (bid - QKV_BLOCKS) * 256 + tid;
        int out = g >> 2;
        int d0 = (g & 3) * 32;
        float partial = 0.f;
        if (out < 8192) {
            partial = dot32_col(ipw + (128 + (out >> 6)) * 128, W2, 64, out & 63, d0);
        } else if (out < 16384) {
            int t = out - 8192;
            partial = dot32_col(ipw + (256 + (t >> 6)) * 128, W2, 64, t & 63, d0);
        } else if (out < 32768) {
            int t = out - 16384;
            partial = dot32_col(pw + (t >> 7) * 256 + 128, outw, 128, t & 127, d0);
        } else if (out < 32896) {
            int t = out - 32768;
            partial = dot32_vec(pw + t * 256 + 128, outb, d0);
        }
        partial += __shfl_xor_sync(0xffffffffu, partial, 1);
        partial += __shfl_xor_sync(0xffffffffu, partial, 2);
        if ((g & 3) == 0) {
            if (out < 8192)         g_wk2[out] = partial;
            else if (out < 16384)   g_wv2[out - 8192] = partial;
            else if (out < 32768)   g_wco[out - 16384] = partial;
            else if (out < 32896)   g_bco[out - 32768] = pb[out - 32768] + partial;
        }
        return;
    }

    __shared__ float As[32][AS_P];
    __shared__ float Bs[32][BS_P];
    __shared__ float bias_s[64];
    int m0 = (bid & 63) * 128, n0 = (bid >> 6) * 64;
    int tx = tid & 15, ty = tid >> 4;

    {
        int o = tid >> 2;
        int d0 = (tid & 3) * 32;
        int n = n0 + o;
        float p = (n >= 128) ? dot32_vec(ipw + n * 128, b2, d0) : 0.f;
        p += __shfl_xor_sync(0xffffffffu, p, 1);
        p += __shfl_xor_sync(0xffffffffu, p, 2);
        if ((tid & 3) == 0) bias_s[o] = ipb[n] + p;
    }

    unsigned long long acc[4][4];
    #pragma unroll
    for (int r = 0; r < 4; r++)
        #pragma unroll
        for (int c = 0; c < 4; c++) acc[r][c] = 0ULL;

    float4 pa[4], pb2[2];
    int rowA[4], kqA[4], rowB[2], kqB[2];
    #pragma unroll
    for (int i = 0; i < 4; i++) { int idx = tid + i * 256; rowA[i] = idx >> 3; kqA[i] = idx & 7; }
    #pragma unroll
    for (int i = 0; i < 2; i++) { int idx = tid + i * 256; rowB[i] = idx >> 3; kqB[i] = idx & 7; }

    #pragma unroll
    for (int i = 0; i < 4; i++) pa[i] = *(const float4*)&X[(m0 + rowA[i]) * 128 + kqA[i] * 4];
    #pragma unroll
    for (int i = 0; i < 2; i++) pb2[i] = *(const float4*)&ipw[(n0 + rowB[i]) * 128 + kqB[i] * 4];

    for (int kc = 0; kc < 4; kc++) {
        #pragma unroll
        for (int i = 0; i < 4; i++) {
            As[kqA[i] * 4 + 0][rowA[i]] = pa[i].x;
            As[kqA[i] * 4 + 1][rowA[i]] = pa[i].y;
            As[kqA[i] * 4 + 2][rowA[i]] = pa[i].z;
            As[kqA[i] * 4 + 3][rowA[i]] = pa[i].w;
        }
        #pragma unroll
        for (int i = 0; i < 2; i++) {
            Bs[kqB[i] * 4 + 0][rowB[i]] = pb2[i].x;
            Bs[kqB[i] * 4 + 1][rowB[i]] = pb2[i].y;
            Bs[kqB[i] * 4 + 2][rowB[i]] = pb2[i].z;
            Bs[kqB[i] * 4 + 3][rowB[i]] = pb2[i].w;
        }
        __syncthreads();
        if (kc < 3) {
            int k0 = (kc + 1) * 32;
            #pragma unroll
            for (int i = 0; i < 4; i++) pa[i] = *(const float4*)&X[(m0 + rowA[i]) * 128 + k0 + kqA[i] * 4];
            #pragma unroll
            for (int i = 0; i < 2; i++) pb2[i] = *(const float4*)&ipw[(n0 + rowB[i]) * 128 + k0 + kqB[i] * 4];
        }
        #pragma unroll
        for (int k = 0; k < 32; k++) {
            F4U a0, a1, b;
            a0.f4 = *(const float4*)&As[k][ty * 8];
            a1.f4 = *(const float4*)&As[k][ty * 8 + 4];
            b.f4  = *(const float4*)&Bs[k][tx * 4];
            unsigned long long bd[4];
            #pragma unroll
            for (int c = 0; c < 4; c++) bd[c] = dup2(b.f[c]);
            #pragma unroll
            for (int c = 0; c < 4; c++) {
                ffma2(acc[0][c], a0.u[0], bd[c]);
                ffma2(acc[1][c], a0.u[1], bd[c]);
                ffma2(acc[2][c], a1.u[0], bd[c]);
                ffma2(acc[3][c], a1.u[1], bd[c]);
            }
        }
        __syncthreads();
    }
    float scale = (n0 < 128) ? QSCALE : 1.0f;
    int n = n0 + tx * 4;
    float4 b4 = *(const float4*)&bias_s[tx * 4];
    #pragma unroll
    for (int r2 = 0; r2 < 4; r2++) {
        float2 p0 = unpk2(acc[r2][0]), p1 = unpk2(acc[r2][1]);
        float2 p2 = unpk2(acc[r2][2]), p3 = unpk2(acc[r2][3]);
        int m = m0 + ty * 8 + r2 * 2;
        float4 lo = make_float4((p0.x + b4.x) * scale, (p1.x + b4.y) * scale,
                                (p2.x + b4.z) * scale, (p3.x + b4.w) * scale);
        float4 hi = make_float4((p0.y + b4.x) * scale, (p1.y + b4.y) * scale,
                                (p2.y + b4.z) * scale, (p3.y + b4.w) * scale);
        *(float4*)&g_y[m * 384 + n] = lo;
        *(float4*)&g_y[(m + 1) * 384 + n] = hi;
    }
}

// ---------------- K3: attention + fused output GEMM ----------------
// phase1: KFt[128][66] + WK2[128][68]; phase2 (same space): VFt[128][65] + WV2T[64][130];
// phase3 overlays: XT[256][68] (k<128 = X dims, k>=128 = ctx dims) + BCO[128];
// WT[256][132] overlays BUF. Total 21760 + 33792 = 55552 floats (217 KB).
#define STK  66
#define STW  68
#define STV  65
#define STVT 130
#define STU  66
#define STXT 68
#define STWT 132
#define OFF_WK2  8448
#define OFF_UG   17152
#define OFF_W1B  21376
#define OFF_P2   21632
#define OFF_BUF  21760
#define ATTN_SMEM_FLOATS (21760 + 256 * 132)

__global__ void __launch_bounds__(512) attn_kernel(const float* __restrict__ pos,
                                                   const float* __restrict__ W1,
                                                   const float* __restrict__ b1,
                                                   const float* __restrict__ XF,
                                                   const float* __restrict__ PW,
                                                   float* __restrict__ OUT)
{
    extern __shared__ float sm[];
    float*  KFt  = sm;                       // phase1 [d][j] stride 66
    float*  WK2  = sm + OFF_WK2;             // phase1 [d][c] stride 68
    float*  VFt  = sm;                       // phase2 [vd][j] stride 65
    float*  WV2T = sm + OFF_WK2;             // phase2 [c][vd] stride 130
    float*  UG   = sm + OFF_UG;              // [j][c] stride 66 : W1·pos_j
    float4* W1B  = (float4*)(sm + OFF_W1B);  // (w1x, w1y, b1, 0)
    float2* P2   = (float2*)(sm + OFF_P2);
    float*  BUF  = sm + OFF_BUF;             // per-warp: TG4[1024] SC4[1024]
    // phase3 overlays (UG/W1B/P2 dead by then):
    float*  XT   = sm;                       // [k][i] 256x68
    float*  BCO  = sm + 256 * STXT;          // [128] at 17408
    float*  WT   = sm + OFF_BUF;             // [256][132] = [P1 ; Wco] transposed

    int s = blockIdx.x, tid = threadIdx.x;
    int w = tid >> 5, lane = tid & 31;
    int base = s * 64;

    // ---- phase-1 loads ----
    #pragma unroll
    for (int it = 0; it < 16; it++) {
        int idx = tid + it * 512;
        int r = idx >> 7, c = idx & 127;
        KFt[c * STK + r] = g_y[(base + r) * 384 + 128 + c];
    }
    #pragma unroll
    for (int it = 0; it < 4; it++) {
        int idx = tid + it * 512;
        int row = idx >> 4, cq = idx & 15;
        *(float4*)&WK2[row * STW + cq * 4] = *(const float4*)&g_wk2[row * 64 + cq * 4];
    }
    if (tid < 64) {
        W1B[tid] = make_float4(W1[tid * 2], W1[tid * 2 + 1], b1[tid], 0.f);
        P2[tid]  = *(const float2*)&pos[(base + tid) * 2];
    }
    __syncthreads();
    #pragma unroll
    for (int it = 0; it < 8; it++) {
        int idx = tid + it * 512;
        int j = idx >> 6, c = idx & 63;
        float4 wb = W1B[c];
        float2 pj = P2[j];
        UG[j * STU + c] = fmaf(wb.x, pj.x, wb.y * pj.y);
    }
    float qreg[4][4];
    #pragma unroll
    for (int q = 0; q < 4; q++) {
        int i = w + q * 16;
        #pragma unroll
        for (int h = 0; h < 4; h++)
            qreg[q][h] = g_y[(base + i) * 384 + h * 32 + lane];
    }
    int c0 = 2 * lane, c1 = c0 + 1;
    float2 pj0 = P2[c0], pj1 = P2[c1];
    float dx0[4], dy0[4], dx1[4], dy1[4];
    #pragma unroll
    for (int q = 0; q < 4; q++) {
        float2 pi = P2[w + q * 16];
        dx0[q] = pj0.x - pi.x; dy0[q] = pj0.y - pi.y;
        dx1[q] = pj1.x - pi.x; dy1[q] = pj1.y - pi.y;
    }
    __syncthreads();

    float* myT  = BUF + w * 2048;
    float* mySC = myT + 1024;

    // ---- score + T pass ----
    unsigned long long spk[4][4], tpk[4][4];
    #pragma unroll
    for (int h = 0; h < 4; h++) {
        unsigned long long tacc[4] = {0ULL, 0ULL, 0ULL, 0ULL};
        unsigned long long sacc[4] = {0ULL, 0ULL, 0ULL, 0ULL};
        #pragma unroll 8
        for (int d = 0; d < 32; d++) {
            int dd = h * 32 + d;
            unsigned long long kk = *(const unsigned long long*)&KFt[dd * STK + c0];
            unsigned long long wk = *(const unsigned long long*)&WK2[dd * STW + c0];
            #pragma unroll
            for (int q = 0; q < 4; q++) {
                unsigned long long qd = dup2(__shfl_sync(0xffffffffu, qreg[q][h], d));
                ffma2(tacc[q], qd, wk);
                ffma2(sacc[q], qd, kk);
            }
        }
        #pragma unroll
        for (int q = 0; q < 4; q++) { tpk[q][h] = tacc[q]; spk[q][h] = sacc[q]; }
    }
    #pragma unroll
    for (int q = 0; q < 4; q++) {
        float2 t0 = unpk2(tpk[q][0]), t1 = unpk2(tpk[q][1]);
        float2 t2 = unpk2(tpk[q][2]), t3 = unpk2(tpk[q][3]);
        *(float4*)&myT[q * 256 + c0 * 4] = make_float4(t0.x, t1.x, t2.x, t3.x);
        *(float4*)&myT[q * 256 + c1 * 4] = make_float4(t0.y, t1.y, t2.y, t3.y);
    }
    unsigned long long aj0_01[4], aj0_23[4], aj1_01[4], aj1_23[4];
    #pragma unroll
    for (int q = 0; q < 4; q++) {
        float2 s0 = unpk2(spk[q][0]), s1 = unpk2(spk[q][1]);
        float2 s2 = unpk2(spk[q][2]), s3 = unpk2(spk[q][3]);
        aj0_01[q] = pk2(s0.x, s1.x); aj0_23[q] = pk2(s2.x, s3.x);
        aj1_01[q] = pk2(s0.y, s1.y); aj1_23[q] = pk2(s2.y, s3.y);
    }
    __syncwarp();

    // ---- rel-encoding contribution ----
    #pragma unroll 4
    for (int c = 0; c < 64; c++) {
        float4 wb = W1B[c];
        #pragma unroll
        for (int q = 0; q < 4; q++) {
            F4U tv; tv.f4 = *(const float4*)&myT[q * 256 + c * 4];
            float h0 = fmaxf(fmaf(wb.x, dx0[q], fmaf(wb.y, dy0[q], wb.z)), 0.f);
            float h1 = fmaxf(fmaf(wb.x, dx1[q], fmaf(wb.y, dy1[q], wb.z)), 0.f);
            unsigned long long h0d = dup2(h0), h1d = dup2(h1);
            ffma2(aj0_01[q], tv.u[0], h0d);
            ffma2(aj0_23[q], tv.u[1], h0d);
            ffma2(aj1_01[q], tv.u[0], h1d);
            ffma2(aj1_23[q], tv.u[1], h1d);
        }
    }
    __syncwarp();

    // ---- softmax ----
    float e0[4][4], e1[4][4];
    #pragma unroll
    for (int q = 0; q < 4; q++) {
        float a0[4], a1[4];
        float2 u;
        u = unpk2(aj0_01[q]); a0[0] = u.x; a0[1] = u.y;
        u = unpk2(aj0_23[q]); a0[2] = u.x; a0[3] = u.y;
        u = unpk2(aj1_01[q]); a1[0] = u.x; a1[1] = u.y;
        u = unpk2(aj1_23[q]); a1[2] = u.x; a1[3] = u.y;
        #pragma unroll
        for (int h = 0; h < 4; h++) {
            float m = fmaxf(a0[h], a1[h]);
            #pragma unroll
            for (int off = 16; off; off >>= 1)
                m = fmaxf(m, __shfl_xor_sync(0xffffffffu, m, off));
            float ex0 = __expf(a0[h] - m), ex1 = __expf(a1[h] - m);
            float ss = ex0 + ex1;
            #pragma unroll
            for (int off = 16; off; off >>= 1)
                ss += __shfl_xor_sync(0xffffffffu, ss, off);
            float rinv = 1.f / ss;
            e0[q][h] = ex0 * rinv;
            e1[q][h] = ex1 * rinv;
        }
    }
    #pragma unroll
    for (int h = 0; h < 4; h++) {
        *(float4*)&mySC[(h * 64 + c0) * 4] = make_float4(e0[0][h], e0[1][h], e0[2][h], e0[3][h]);
        *(float4*)&mySC[(h * 64 + c1) * 4] = make_float4(e1[0][h], e1[1][h], e1[2][h], e1[3][h]);
    }
    __syncwarp();

    // ---- g-loop ----
    float vi0[4], vi1[4];
    {
        float b1c0 = W1B[c0].z, b1c1 = W1B[c1].z;
        #pragma unroll
        for (int q = 0; q < 4; q++) {
            int i = w + q * 16;
            vi0[q] = UG[i * STU + c0] - b1c0;
            vi1[q] = UG[i * STU + c1] - b1c1;
        }
    }
    float g0[4][4], g1[4][4];
    #pragma unroll
    for (int q = 0; q < 4; q++)
        #pragma unroll
        for (int h = 0; h < 4; h++) { g0[q][h] = 0.f; g1[q][h] = 0.f; }
    #pragma unroll 2
    for (int j = 0; j < 64; j++) {
        float2 ug = unpk2(*(const unsigned long long*)&UG[j * STU + c0]);
        float h0q[4], h1q[4];
        #pragma unroll
        for (int q = 0; q < 4; q++) {
            h0q[q] = fmaxf(ug.x - vi0[q], 0.f);
            h1q[q] = fmaxf(ug.y - vi1[q], 0.f);
        }
        #pragma unroll
        for (int h = 0; h < 4; h++) {
            F4U a4; a4.f4 = *(const float4*)&mySC[(h * 64 + j) * 4];
            #pragma unroll
            for (int q = 0; q < 4; q++) {
                g0[q][h] = fmaf(a4.f[q], h0q[q], g0[q][h]);
                g1[q][h] = fmaf(a4.f[q], h1q[q], g1[q][h]);
            }
        }
    }
    #pragma unroll
    for (int h = 0; h < 4; h++) {
        *(float4*)&myT[(h * 64 + c0) * 4] = make_float4(g0[0][h], g0[1][h], g0[2][h], g0[3][h]);
        *(float4*)&myT[(h * 64 + c1) * 4] = make_float4(g1[0][h], g1[1][h], g1[2][h], g1[3][h]);
    }

    // ---- phase-2 loads: VFt + WV2T into dead KFt/WK2 regions ----
    __syncthreads();
    #pragma unroll
    for (int it = 0; it < 16; it++) {
        int idx = tid + it * 512;
        int r = idx >> 7, c = idx & 127;
        VFt[c * STV + r] = g_y[(base + r) * 384 + 256 + c];
    }
    #pragma unroll
    for (int it = 0; it < 16; it++) {
        int idx = tid + it * 512;
        int vd = idx >> 6, c = idx & 63;
        WV2T[c * STVT + vd] = g_wv2[vd * 64 + c];
    }
    __syncthreads();

    // ---- out-phase: ctx = attn@VF + g@WV2^T  (held in registers) ----
    unsigned long long ctxp01[4], ctxp23[4];
    #pragma unroll
    for (int h = 0; h < 4; h++) {
        unsigned long long p01 = 0ULL, p23 = 0ULL;
        int vd = h * 32 + lane;
        const float* vr = VFt + vd * STV;
        #pragma unroll 4
        for (int j = 0; j < 64; j++) {
            unsigned long long vv = dup2(vr[j]);
            F4U a4; a4.f4 = *(const float4*)&mySC[(h * 64 + j) * 4];
            ffma2(p01, a4.u[0], vv);
            ffma2(p23, a4.u[1], vv);
        }
        const float* wc = WV2T + vd;
        #pragma unroll 4
        for (int c = 0; c < 64; c++) {
            unsigned long long wv = dup2(wc[c * STVT]);
            F4U g4; g4.f4 = *(const float4*)&myT[(h * 64 + c) * 4];
            ffma2(p01, g4.u[0], wv);
            ffma2(p23, g4.u[1], wv);
        }
        ctxp01[h] = p01; ctxp23[h] = p23;
    }

    // ---- phase-3: build XT[k][i] (X dims then ctx dims), BCO, WT=[P1;Wco]^T ----
    __syncthreads();    // VFt/WV2T, BUF data, UG, W1B, P2 all dead
    #pragma unroll
    for (int h = 0; h < 4; h++) {
        int vd = h * 32 + lane;
        float2 u01 = unpk2(ctxp01[h]), u23 = unpk2(ctxp23[h]);
        XT[(128 + vd) * STXT + (w +  0)] = u01.x;
        XT[(128 + vd) * STXT + (w + 16)] = u01.y;
        XT[(128 + vd) * STXT + (w + 32)] = u23.x;
        XT[(128 + vd) * STXT + (w + 48)] = u23.y;
    }
    #pragma unroll
    for (int it = 0; it < 4; it++) {        // X tile transposed: XT[c][i]
        int idx = tid + it * 512;
        int i = idx >> 5, cq = idx & 31;
        float4 v = *(const float4*)&XF[(base + i) * 128 + cq * 4];
        XT[(cq * 4 + 0) * STXT + i] = v.x;
        XT[(cq * 4 + 1) * STXT + i] = v.y;
        XT[(cq * 4 + 2) * STXT + i] = v.z;
        XT[(cq * 4 + 3) * STXT + i] = v.w;
    }
    if (tid < 128) BCO[tid] = g_bco[tid];
    #pragma unroll
    for (int it = 0; it < 8; it++) {        // P1 -> WT rows 0..127 (transposed)
        int idx = tid + it * 512;
        int n = idx >> 5, kq = (idx & 31) * 4;
        float4 v = *(const float4*)&PW[n * 256 + kq];
        WT[(kq + 0) * STWT + n] = v.x;
        WT[(kq + 1) * STWT + n] = v.y;
        WT[(kq + 2) * STWT + n] = v.z;
        WT[(kq + 3) * STWT + n] = v.w;
    }
    #pragma unroll
    for (int it = 0; it < 8; it++) {        // Wco -> WT rows 128..255 (transposed)
        int idx = tid + it * 512;
        int n = idx >> 5, kq = (idx & 31) * 4;
        float4 v = *(const float4*)&g_wco[n * 128 + kq];
        WT[(128 + kq + 0) * STWT + n] = v.x;
        WT[(128 + kq + 1) * STWT + n] = v.y;
        WT[(128 + kq + 2) * STWT + n] = v.z;
        WT[(128 + kq + 3) * STWT + n] = v.w;
    }
    __syncthreads();

    // ---- fused output GEMM: out[i][n] = sum_k XT[k][i] * WT[k][n] + bco ----
    // warp w: rows w*4..w*4+3 (A broadcast); lane: cols lane*4..+3 (B conflict-free)
    {
        unsigned long long ga[4][2];
        #pragma unroll
        for (int m = 0; m < 4; m++) { ga[m][0] = 0ULL; ga[m][1] = 0ULL; }
        #pragma unroll 8
        for (int k = 0; k < 256; k++) {
            F4U a; a.f4 = *(const float4*)&XT[k * STXT + w * 4];
            F4U b; b.f4 = *(const float4*)&WT[k * STWT + lane * 4];
            #pragma unroll
            for (int m = 0; m < 4; m++) {
                unsigned long long ad = dup2(a.f[m]);
                ffma2(ga[m][0], ad, b.u[0]);
                ffma2(ga[m][1], ad, b.u[1]);
            }
        }
        F4U bc; bc.f4 = *(const float4*)&BCO[lane * 4];
        #pragma unroll
        for (int m = 0; m < 4; m++) {
            float2 r0 = unpk2(ga[m][0]), r1 = unpk2(ga[m][1]);
            float4 o = make_float4(r0.x + bc.f[0], r0.y + bc.f[1],
                                   r1.x + bc.f[2], r1.y + bc.f[3]);
            *(float4*)&OUT[(base + w * 4 + m) * 128 + lane * 4] = o;
        }
    }
}

// ---------------- launch ----------------
extern "C" void kernel_launch(void* const* d_in, const int* in_sizes, int n_in,
                              void* d_out, int out_size)
{
    const float* node_features = (const float*)d_in[0];
    const float* positions     = (const float*)d_in[1];
    const float* W1            = (const float*)d_in[2];
    const float* b1            = (const float*)d_in[3];
    const float* W2            = (const float*)d_in[4];
    const float* b2            = (const float*)d_in[5];
    const float* in_proj_w     = (const float*)d_in[6];
    const float* in_proj_b     = (const float*)d_in[7];
    const float* out_w         = (const float*)d_in[8];
    const float* out_b         = (const float*)d_in[9];
    const float* proj_w        = (const float*)d_in[10];
    const float* proj_b        = (const float*)d_in[11];
    float* out = (float*)d_out;

    size_t attn_smem = (size_t)ATTN_SMEM_FLOATS * sizeof(float);
    cudaFuncSetAttribute(attn_kernel, cudaFuncAttributeMaxDynamicSharedMemorySize,
                         (int)attn_smem);

    qkv_prep<<<QKV_BLOCKS + 514, 256>>>(node_features, in_proj_w, in_proj_b,
                                        W2, b2, out_w, out_b, proj_w, proj_b);
    attn_kernel<<<S_SCENES, 512, attn_smem>>>(positions, W1, b1,
                                              node_features, proj_w, out);
}

// round 17
// speedup vs baseline: 1.0642x; 1.0642x over previous
#include <cuda_runtime.h>
#include <math.h>

#define S_SCENES 128
#define N_PED    64
#define HID      128
#define TOTAL    (S_SCENES * N_PED)   // 8192
#define QSCALE   0.17677669529663687f // 1/sqrt(32)

// ---------------- device scratch ----------------
__device__ float g_y[TOTAL * 384];    // q | kf | vf  (q pre-scaled)
__device__ float g_wk2[HID * 64];     // Wk @ W2
__device__ float g_wv2[HID * 64];     // Wv @ W2
__device__ float g_wco[HID * HID];    // P2 @ out_w
__device__ float g_bco[HID];          // proj_b + P2 @ out_b

// ---------------- f32x2 helpers ----------------
__device__ __forceinline__ unsigned long long dup2(float x) {
    unsigned long long r;
    asm("mov.b64 %0, {%1, %1};" : "=l"(r) : "r"(__float_as_uint(x)));
    return r;
}
__device__ __forceinline__ unsigned long long pk2(float lo, float hi) {
    unsigned long long r;
    asm("mov.b64 %0, {%1, %2};" : "=l"(r) : "r"(__float_as_uint(lo)), "r"(__float_as_uint(hi)));
    return r;
}
__device__ __forceinline__ void ffma2(unsigned long long& d,
                                      unsigned long long a, unsigned long long b) {
    asm("fma.rn.f32x2 %0, %1, %2, %0;" : "+l"(d) : "l"(a), "l"(b));
}
__device__ __forceinline__ float2 unpk2(unsigned long long v) {
    unsigned lo, hi;
    asm("mov.b64 {%0, %1}, %2;" : "=r"(lo), "=r"(hi) : "l"(v));
    return make_float2(__uint_as_float(lo), __uint_as_float(hi));
}
union F4U { float4 f4; unsigned long long u[2]; float f[4]; };

// ---------------- dot helpers (prep) ----------------
__device__ __forceinline__ float dot32_col(const float* __restrict__ row,
                                           const float* __restrict__ colbase,
                                           int ldc, int c, int d0) {
    float a0 = 0.f, a1 = 0.f, a2 = 0.f, a3 = 0.f;
    #pragma unroll
    for (int dd = 0; dd < 32; dd += 4) {
        int d = d0 + dd;
        float4 wv = *(const float4*)&row[d];
        a0 = fmaf(wv.x, colbase[(d + 0) * ldc + c], a0);
        a1 = fmaf(wv.y, colbase[(d + 1) * ldc + c], a1);
        a2 = fmaf(wv.z, colbase[(d + 2) * ldc + c], a2);
        a3 = fmaf(wv.w, colbase[(d + 3) * ldc + c], a3);
    }
    return (a0 + a1) + (a2 + a3);
}
__device__ __forceinline__ float dot32_vec(const float* __restrict__ a,
                                           const float* __restrict__ b, int d0) {
    float a0 = 0.f, a1 = 0.f, a2 = 0.f, a3 = 0.f;
    #pragma unroll
    for (int dd = 0; dd < 32; dd += 4) {
        int d = d0 + dd;
        float4 av = *(const float4*)&a[d];
        float4 bv = *(const float4*)&b[d];
        a0 = fmaf(av.x, bv.x, a0);
        a1 = fmaf(av.y, bv.y, a1);
        a2 = fmaf(av.z, bv.z, a2);
        a3 = fmaf(av.w, bv.w, a3);
    }
    return (a0 + a1) + (a2 + a3);
}

// ---------------- Combined G1 + prep kernel (R15 proven) ----------------
#define AS_P 132
#define BS_P 68
#define QKV_BLOCKS 384

__global__ void __launch_bounds__(256) qkv_prep(const float* __restrict__ X,
                                                const float* __restrict__ ipw,
                                                const float* __restrict__ ipb,
                                                const float* __restrict__ W2,
                                                const float* __restrict__ b2,
                                                const float* __restrict__ outw,
                                                const float* __restrict__ outb,
                                                const float* __restrict__ pw,
                                                const float* __restrict__ pb)
{
    int bid = blockIdx.x;
    int tid = threadIdx.x;

    if (bid >= QKV_BLOCKS) {
        int g = (bid - QKV_BLOCKS) * 256 + tid;
        int out = g >> 2;
        int d0 = (g & 3) * 32;
        float partial = 0.f;
        if (out < 8192) {
            partial = dot32_col(ipw + (128 + (out >> 6)) * 128, W2, 64, out & 63, d0);
        } else if (out < 16384) {
            int t = out - 8192;
            partial = dot32_col(ipw + (256 + (t >> 6)) * 128, W2, 64, t & 63, d0);
        } else if (out < 32768) {
            int t = out - 16384;
            partial = dot32_col(pw + (t >> 7) * 256 + 128, outw, 128, t & 127, d0);
        } else if (out < 32896) {
            int t = out - 32768;
            partial = dot32_vec(pw + t * 256 + 128, outb, d0);
        }
        partial += __shfl_xor_sync(0xffffffffu, partial, 1);
        partial += __shfl_xor_sync(0xffffffffu, partial, 2);
        if ((g & 3) == 0) {
            if (out < 8192)         g_wk2[out] = partial;
            else if (out < 16384)   g_wv2[out - 8192] = partial;
            else if (out < 32768)   g_wco[out - 16384] = partial;
            else if (out < 32896)   g_bco[out - 32768] = pb[out - 32768] + partial;
        }
        return;
    }

    __shared__ float As[32][AS_P];
    __shared__ float Bs[32][BS_P];
    __shared__ float bias_s[64];
    int m0 = (bid & 63) * 128, n0 = (bid >> 6) * 64;
    int tx = tid & 15, ty = tid >> 4;

    {
        int o = tid >> 2;
        int d0 = (tid & 3) * 32;
        int n = n0 + o;
        float p = (n >= 128) ? dot32_vec(ipw + n * 128, b2, d0) : 0.f;
        p += __shfl_xor_sync(0xffffffffu, p, 1);
        p += __shfl_xor_sync(0xffffffffu, p, 2);
        if ((tid & 3) == 0) bias_s[o] = ipb[n] + p;
    }

    unsigned long long acc[4][4];
    #pragma unroll
    for (int r = 0; r < 4; r++)
        #pragma unroll
        for (int c = 0; c < 4; c++) acc[r][c] = 0ULL;

    float4 pa[4], pb2[2];
    int rowA[4], kqA[4], rowB[2], kqB[2];
    #pragma unroll
    for (int i = 0; i < 4; i++) { int idx = tid + i * 256; rowA[i] = idx >> 3; kqA[i] = idx & 7; }
    #pragma unroll
    for (int i = 0; i < 2; i++) { int idx = tid + i * 256; rowB[i] = idx >> 3; kqB[i] = idx & 7; }

    #pragma unroll
    for (int i = 0; i < 4; i++) pa[i] = *(const float4*)&X[(m0 + rowA[i]) * 128 + kqA[i] * 4];
    #pragma unroll
    for (int i = 0; i < 2; i++) pb2[i] = *(const float4*)&ipw[(n0 + rowB[i]) * 128 + kqB[i] * 4];

    for (int kc = 0; kc < 4; kc++) {
        #pragma unroll
        for (int i = 0; i < 4; i++) {
            As[kqA[i] * 4 + 0][rowA[i]] = pa[i].x;
            As[kqA[i] * 4 + 1][rowA[i]] = pa[i].y;
            As[kqA[i] * 4 + 2][rowA[i]] = pa[i].z;
            As[kqA[i] * 4 + 3][rowA[i]] = pa[i].w;
        }
        #pragma unroll
        for (int i = 0; i < 2; i++) {
            Bs[kqB[i] * 4 + 0][rowB[i]] = pb2[i].x;
            Bs[kqB[i] * 4 + 1][rowB[i]] = pb2[i].y;
            Bs[kqB[i] * 4 + 2][rowB[i]] = pb2[i].z;
            Bs[kqB[i] * 4 + 3][rowB[i]] = pb2[i].w;
        }
        __syncthreads();
        if (kc < 3) {
            int k0 = (kc + 1) * 32;
            #pragma unroll
            for (int i = 0; i < 4; i++) pa[i] = *(const float4*)&X[(m0 + rowA[i]) * 128 + k0 + kqA[i] * 4];
            #pragma unroll
            for (int i = 0; i < 2; i++) pb2[i] = *(const float4*)&ipw[(n0 + rowB[i]) * 128 + k0 + kqB[i] * 4];
        }
        #pragma unroll
        for (int k = 0; k < 32; k++) {
            F4U a0, a1, b;
            a0.f4 = *(const float4*)&As[k][ty * 8];
            a1.f4 = *(const float4*)&As[k][ty * 8 + 4];
            b.f4  = *(const float4*)&Bs[k][tx * 4];
            unsigned long long bd[4];
            #pragma unroll
            for (int c = 0; c < 4; c++) bd[c] = dup2(b.f[c]);
            #pragma unroll
            for (int c = 0; c < 4; c++) {
                ffma2(acc[0][c], a0.u[0], bd[c]);
                ffma2(acc[1][c], a0.u[1], bd[c]);
                ffma2(acc[2][c], a1.u[0], bd[c]);
                ffma2(acc[3][c], a1.u[1], bd[c]);
            }
        }
        __syncthreads();
    }
    float scale = (n0 < 128) ? QSCALE : 1.0f;
    int n = n0 + tx * 4;
    float4 b4 = *(const float4*)&bias_s[tx * 4];
    #pragma unroll
    for (int r2 = 0; r2 < 4; r2++) {
        float2 p0 = unpk2(acc[r2][0]), p1 = unpk2(acc[r2][1]);
        float2 p2 = unpk2(acc[r2][2]), p3 = unpk2(acc[r2][3]);
        int m = m0 + ty * 8 + r2 * 2;
        float4 lo = make_float4((p0.x + b4.x) * scale, (p1.x + b4.y) * scale,
                                (p2.x + b4.z) * scale, (p3.x + b4.w) * scale);
        float4 hi = make_float4((p0.y + b4.x) * scale, (p1.y + b4.y) * scale,
                                (p2.y + b4.z) * scale, (p3.y + b4.w) * scale);
        *(float4*)&g_y[m * 384 + n] = lo;
        *(float4*)&g_y[(m + 1) * 384 + n] = hi;
    }
}

// ---------------- K3: attention + fused output GEMM (R15 layout, vectorized A-loads) ----------------
#define STK  66
#define STW  68
#define STV  65
#define STVT 130
#define STU  66
#define OFF_WK2  8448
#define OFF_UG   17152
#define OFF_W1B  21376
#define OFF_P2   21632
#define OFF_BUF  21760
#define ATTN_SMEM_FLOATS (21760 + 256 * 130)

__global__ void __launch_bounds__(512) attn_kernel(const float* __restrict__ pos,
                                                   const float* __restrict__ W1,
                                                   const float* __restrict__ b1,
                                                   const float* __restrict__ XF,
                                                   const float* __restrict__ PW,
                                                   float* __restrict__ OUT)
{
    extern __shared__ float sm[];
    float*  KFt  = sm;                       // phase1 [d][j] stride 66
    float*  WK2  = sm + OFF_WK2;             // phase1 [d][c] stride 68
    float*  VFt  = sm;                       // phase2 [vd][j] stride 65
    float*  WV2T = sm + OFF_WK2;             // phase2 [c][vd] stride 130
    float*  UG   = sm + OFF_UG;              // [j][c] stride 66 : W1·pos_j
    float4* W1B  = (float4*)(sm + OFF_W1B);  // (w1x, w1y, b1, 0)
    float2* P2   = (float2*)(sm + OFF_P2);
    float*  BUF  = sm + OFF_BUF;             // per-warp: TG4[1024] SC4[1024]
    // phase3 overlays:
    float*  CTXs = sm;                       // [i][d] 64x128
    float*  Xs   = sm + 8192;                // [i][d] 64x128
    float*  BCO  = sm + 16384;               // [128]
    float*  WT   = sm + OFF_BUF;             // [256][130] = [P1 ; Wco] transposed

    int s = blockIdx.x, tid = threadIdx.x;
    int w = tid >> 5, lane = tid & 31;
    int base = s * 64;

    // ---- phase-1 loads ----
    #pragma unroll
    for (int it = 0; it < 16; it++) {
        int idx = tid + it * 512;
        int r = idx >> 7, c = idx & 127;
        KFt[c * STK + r] = g_y[(base + r) * 384 + 128 + c];
    }
    #pragma unroll
    for (int it = 0; it < 4; it++) {
        int idx = tid + it * 512;
        int row = idx >> 4, cq = idx & 15;
        *(float4*)&WK2[row * STW + cq * 4] = *(const float4*)&g_wk2[row * 64 + cq * 4];
    }
    if (tid < 64) {
        W1B[tid] = make_float4(W1[tid * 2], W1[tid * 2 + 1], b1[tid], 0.f);
        P2[tid]  = *(const float2*)&pos[(base + tid) * 2];
    }
    __syncthreads();
    #pragma unroll
    for (int it = 0; it < 8; it++) {
        int idx = tid + it * 512;
        int j = idx >> 6, c = idx & 63;
        float4 wb = W1B[c];
        float2 pj = P2[j];
        UG[j * STU + c] = fmaf(wb.x, pj.x, wb.y * pj.y);
    }
    float qreg[4][4];
    #pragma unroll
    for (int q = 0; q < 4; q++) {
        int i = w + q * 16;
        #pragma unroll
        for (int h = 0; h < 4; h++)
            qreg[q][h] = g_y[(base + i) * 384 + h * 32 + lane];
    }
    int c0 = 2 * lane, c1 = c0 + 1;
    float2 pj0 = P2[c0], pj1 = P2[c1];
    float dx0[4], dy0[4], dx1[4], dy1[4];
    #pragma unroll
    for (int q = 0; q < 4; q++) {
        float2 pi = P2[w + q * 16];
        dx0[q] = pj0.x - pi.x; dy0[q] = pj0.y - pi.y;
        dx1[q] = pj1.x - pi.x; dy1[q] = pj1.y - pi.y;
    }
    __syncthreads();

    float* myT  = BUF + w * 2048;
    float* mySC = myT + 1024;

    // ---- score + T pass ----
    unsigned long long spk[4][4], tpk[4][4];
    #pragma unroll
    for (int h = 0; h < 4; h++) {
        unsigned long long tacc[4] = {0ULL, 0ULL, 0ULL, 0ULL};
        unsigned long long sacc[4] = {0ULL, 0ULL, 0ULL, 0ULL};
        #pragma unroll 8
        for (int d = 0; d < 32; d++) {
            int dd = h * 32 + d;
            unsigned long long kk = *(const unsigned long long*)&KFt[dd * STK + c0];
            unsigned long long wk = *(const unsigned long long*)&WK2[dd * STW + c0];
            #pragma unroll
            for (int q = 0; q < 4; q++) {
                unsigned long long qd = dup2(__shfl_sync(0xffffffffu, qreg[q][h], d));
                ffma2(tacc[q], qd, wk);
                ffma2(sacc[q], qd, kk);
            }
        }
        #pragma unroll
        for (int q = 0; q < 4; q++) { tpk[q][h] = tacc[q]; spk[q][h] = sacc[q]; }
    }
    #pragma unroll
    for (int q = 0; q < 4; q++) {
        float2 t0 = unpk2(tpk[q][0]), t1 = unpk2(tpk[q][1]);
        float2 t2 = unpk2(tpk[q][2]), t3 = unpk2(tpk[q][3]);
        *(float4*)&myT[q * 256 + c0 * 4] = make_float4(t0.x, t1.x, t2.x, t3.x);
        *(float4*)&myT[q * 256 + c1 * 4] = make_float4(t0.y, t1.y, t2.y, t3.y);
    }
    unsigned long long aj0_01[4], aj0_23[4], aj1_01[4], aj1_23[4];
    #pragma unroll
    for (int q = 0; q < 4; q++) {
        float2 s0 = unpk2(spk[q][0]), s1 = unpk2(spk[q][1]);
        float2 s2 = unpk2(spk[q][2]), s3 = unpk2(spk[q][3]);
        aj0_01[q] = pk2(s0.x, s1.x); aj0_23[q] = pk2(s2.x, s3.x);
        aj1_01[q] = pk2(s0.y, s1.y); aj1_23[q] = pk2(s2.y, s3.y);
    }
    __syncwarp();

    // ---- rel-encoding contribution ----
    #pragma unroll 4
    for (int c = 0; c < 64; c++) {
        float4 wb = W1B[c];
        #pragma unroll
        for (int q = 0; q < 4; q++) {
            F4U tv; tv.f4 = *(const float4*)&myT[q * 256 + c * 4];
            float h0 = fmaxf(fmaf(wb.x, dx0[q], fmaf(wb.y, dy0[q], wb.z)), 0.f);
            float h1 = fmaxf(fmaf(wb.x, dx1[q], fmaf(wb.y, dy1[q], wb.z)), 0.f);
            unsigned long long h0d = dup2(h0), h1d = dup2(h1);
            ffma2(aj0_01[q], tv.u[0], h0d);
            ffma2(aj0_23[q], tv.u[1], h0d);
            ffma2(aj1_01[q], tv.u[0], h1d);
            ffma2(aj1_23[q], tv.u[1], h1d);
        }
    }
    __syncwarp();

    // ---- softmax ----
    float e0[4][4], e1[4][4];
    #pragma unroll
    for (int q = 0; q < 4; q++) {
        float a0[4], a1[4];
        float2 u;
        u = unpk2(aj0_01[q]); a0[0] = u.x; a0[1] = u.y;
        u = unpk2(aj0_23[q]); a0[2] = u.x; a0[3] = u.y;
        u = unpk2(aj1_01[q]); a1[0] = u.x; a1[1] = u.y;
        u = unpk2(aj1_23[q]); a1[2] = u.x; a1[3] = u.y;
        #pragma unroll
        for (int h = 0; h < 4; h++) {
            float m = fmaxf(a0[h], a1[h]);
            #pragma unroll
            for (int off = 16; off; off >>= 1)
                m = fmaxf(m, __shfl_xor_sync(0xffffffffu, m, off));
            float ex0 = __expf(a0[h] - m), ex1 = __expf(a1[h] - m);
            float ss = ex0 + ex1;
            #pragma unroll
            for (int off = 16; off; off >>= 1)
                ss += __shfl_xor_sync(0xffffffffu, ss, off);
            float rinv = 1.f / ss;
            e0[q][h] = ex0 * rinv;
            e1[q][h] = ex1 * rinv;
        }
    }
    #pragma unroll
    for (int h = 0; h < 4; h++) {
        *(float4*)&mySC[(h * 64 + c0) * 4] = make_float4(e0[0][h], e0[1][h], e0[2][h], e0[3][h]);
        *(float4*)&mySC[(h * 64 + c1) * 4] = make_float4(e1[0][h], e1[1][h], e1[2][h], e1[3][h]);
    }
    __syncwarp();

    // ---- g-loop ----
    float vi0[4], vi1[4];
    {
        float b1c0 = W1B[c0].z, b1c1 = W1B[c1].z;
        #pragma unroll
        for (int q = 0; q < 4; q++) {
            int i = w + q * 16;
            vi0[q] = UG[i * STU + c0] - b1c0;
            vi1[q] = UG[i * STU + c1] - b1c1;
        }
    }
    float g0[4][4], g1[4][4];
    #pragma unroll
    for (int q = 0; q < 4; q++)
        #pragma unroll
        for (int h = 0; h < 4; h++) { g0[q][h] = 0.f; g1[q][h] = 0.f; }
    #pragma unroll 2
    for (int j = 0; j < 64; j++) {
        float2 ug = unpk2(*(const unsigned long long*)&UG[j * STU + c0]);
        float h0q[4], h1q[4];
        #pragma unroll
        for (int q = 0; q < 4; q++) {
            h0q[q] = fmaxf(ug.x - vi0[q], 0.f);
            h1q[q] = fmaxf(ug.y - vi1[q], 0.f);
        }
        #pragma unroll
        for (int h = 0; h < 4; h++) {
            F4U a4; a4.f4 = *(const float4*)&mySC[(h * 64 + j) * 4];
            #pragma unroll
            for (int q = 0; q < 4; q++) {
                g0[q][h] = fmaf(a4.f[q], h0q[q], g0[q][h]);
                g1[q][h] = fmaf(a4.f[q], h1q[q], g1[q][h]);
            }
        }
    }
    #pragma unroll
    for (int h = 0; h < 4; h++) {
        *(float4*)&myT[(h * 64 + c0) * 4] = make_float4(g0[0][h], g0[1][h], g0[2][h], g0[3][h]);
        *(float4*)&myT[(h * 64 + c1) * 4] = make_float4(g1[0][h], g1[1][h], g1[2][h], g1[3][h]);
    }

    // ---- phase-2 loads: VFt + WV2T into dead KFt/WK2 regions ----
    __syncthreads();
    #pragma unroll
    for (int it = 0; it < 16; it++) {
        int idx = tid + it * 512;
        int r = idx >> 7, c = idx & 127;
        VFt[c * STV + r] = g_y[(base + r) * 384 + 256 + c];
    }
    #pragma unroll
    for (int it = 0; it < 16; it++) {
        int idx = tid + it * 512;
        int vd = idx >> 6, c = idx & 63;
        WV2T[c * STVT + vd] = g_wv2[vd * 64 + c];
    }
    __syncthreads();

    // ---- out-phase: ctx = attn@VF + g@WV2^T  (held in registers) ----
    unsigned long long ctxp01[4], ctxp23[4];
    #pragma unroll
    for (int h = 0; h < 4; h++) {
        unsigned long long p01 = 0ULL, p23 = 0ULL;
        int vd = h * 32 + lane;
        const float* vr = VFt + vd * STV;
        #pragma unroll 4
        for (int j = 0; j < 64; j++) {
            unsigned long long vv = dup2(vr[j]);
            F4U a4; a4.f4 = *(const float4*)&mySC[(h * 64 + j) * 4];
            ffma2(p01, a4.u[0], vv);
            ffma2(p23, a4.u[1], vv);
        }
        const float* wc = WV2T + vd;
        #pragma unroll 4
        for (int c = 0; c < 64; c++) {
            unsigned long long wv = dup2(wc[c * STVT]);
            F4U g4; g4.f4 = *(const float4*)&myT[(h * 64 + c) * 4];
            ffma2(p01, g4.u[0], wv);
            ffma2(p23, g4.u[1], wv);
        }
        ctxp01[h] = p01; ctxp23[h] = p23;
    }

    // ---- phase-3: scatter ctx, load X tile, bco, and WT=[P1;Wco]^T ----
    __syncthreads();    // VFt/WV2T and all BUF data now dead
    #pragma unroll
    for (int h = 0; h < 4; h++) {
        int vd = h * 32 + lane;
        float2 u01 = unpk2(ctxp01[h]), u23 = unpk2(ctxp23[h]);
        CTXs[(w +  0) * 128 + vd] = u01.x;
        CTXs[(w + 16) * 128 + vd] = u01.y;
        CTXs[(w + 32) * 128 + vd] = u23.x;
        CTXs[(w + 48) * 128 + vd] = u23.y;
    }
    #pragma unroll
    for (int it = 0; it < 4; it++) {        // X tile: 8192 floats via float4
        int idx = tid + it * 512;
        int i = idx >> 5, kq = idx & 31;
        *(float4*)&Xs[i * 128 + kq * 4] = *(const float4*)&XF[(base + i) * 128 + kq * 4];
    }
    if (tid < 128) BCO[tid] = g_bco[tid];
    #pragma unroll
    for (int it = 0; it < 8; it++) {        // P1 -> WT rows 0..127 (transposed)
        int idx = tid + it * 512;
        int n = idx >> 5, kq = (idx & 31) * 4;
        float4 v = *(const float4*)&PW[n * 256 + kq];
        WT[(kq + 0) * 130 + n] = v.x;
        WT[(kq + 1) * 130 + n] = v.y;
        WT[(kq + 2) * 130 + n] = v.z;
        WT[(kq + 3) * 130 + n] = v.w;
    }
    #pragma unroll
    for (int it = 0; it < 8; it++) {        // Wco -> WT rows 128..255 (transposed)
        int idx = tid + it * 512;
        int n = idx >> 5, kq = (idx & 31) * 4;
        float4 v = *(const float4*)&g_wco[n * 128 + kq];
        WT[(128 + kq + 0) * 130 + n] = v.x;
        WT[(128 + kq + 1) * 130 + n] = v.y;
        WT[(128 + kq + 2) * 130 + n] = v.z;
        WT[(128 + kq + 3) * 130 + n] = v.w;
    }
    __syncthreads();

    // ---- fused output GEMM: out[i][n] = Xs@P1^T + CTXs@Wco^T + bco ----
    // A-loads vectorized: one LDS.128 broadcast per row serves 4 k's.
    {
        int i0 = w * 4;
        int n0 = 2 * lane, n1 = 2 * lane + 64;
        unsigned long long ga[4][2];
        #pragma unroll
        for (int ii = 0; ii < 4; ii++) { ga[ii][0] = 0ULL; ga[ii][1] = 0ULL; }
        #pragma unroll 4
        for (int k4 = 0; k4 < 32; k4++) {
            F4U av[4];
            #pragma unroll
            for (int ii = 0; ii < 4; ii++)
                av[ii].f4 = *(const float4*)&Xs[(i0 + ii) * 128 + k4 * 4];
            #pragma unroll
            for (int u = 0; u < 4; u++) {
                int k = k4 * 4 + u;
                unsigned long long w0 = *(const unsigned long long*)&WT[k * 130 + n0];
                unsigned long long w1 = *(const unsigned long long*)&WT[k * 130 + n1];
                #pragma unroll
                for (int ii = 0; ii < 4; ii++) {
                    unsigned long long ad = dup2(av[ii].f[u]);
                    ffma2(ga[ii][0], ad, w0);
                    ffma2(ga[ii][1], ad, w1);
                }
            }
        }
        #pragma unroll 4
        for (int k4 = 0; k4 < 32; k4++) {
            F4U av[4];
            #pragma unroll
            for (int ii = 0; ii < 4; ii++)
                av[ii].f4 = *(const float4*)&CTXs[(i0 + ii) * 128 + k4 * 4];
            #pragma unroll
            for (int u = 0; u < 4; u++) {
                int k = k4 * 4 + u;
                unsigned long long w0 = *(const unsigned long long*)&WT[(128 + k) * 130 + n0];
                unsigned long long w1 = *(const unsigned long long*)&WT[(128 + k) * 130 + n1];
                #pragma unroll
                for (int ii = 0; ii < 4; ii++) {
                    unsigned long long ad = dup2(av[ii].f[u]);
                    ffma2(ga[ii][0], ad, w0);
                    ffma2(ga[ii][1], ad, w1);
                }
            }
        }
        float2 bc0 = *(const float2*)&BCO[n0];
        float2 bc1 = *(const float2*)&BCO[n1];
        #pragma unroll
        for (int ii = 0; ii < 4; ii++) {
            float2 r0 = unpk2(ga[ii][0]), r1 = unpk2(ga[ii][1]);
            *(float2*)&OUT[(base + i0 + ii) * 128 + n0] = make_float2(r0.x + bc0.x, r0.y + bc0.y);
            *(float2*)&OUT[(base + i0 + ii) * 128 + n1] = make_float2(r1.x + bc1.x, r1.y + bc1.y);
        }
    }
}

// ---------------- launch ----------------
extern "C" void kernel_launch(void* const* d_in, const int* in_sizes, int n_in,
                              void* d_out, int out_size)
{
    const float* node_features = (const float*)d_in[0];
    const float* positions     = (const float*)d_in[1];
    const float* W1            = (const float*)d_in[2];
    const float* b1            = (const float*)d_in[3];
    const float* W2            = (const float*)d_in[4];
    const float* b2            = (const float*)d_in[5];
    const float* in_proj_w     = (const float*)d_in[6];
    const float* in_proj_b     = (const float*)d_in[7];
    const float* out_w         = (const float*)d_in[8];
    const float* out_b         = (const float*)d_in[9];
    const float* proj_w        = (const float*)d_in[10];
    const float* proj_b        = (const float*)d_in[11];
    float* out = (float*)d_out;

    size_t attn_smem = (size_t)ATTN_SMEM_FLOATS * sizeof(float);
    cudaFuncSetAttribute(attn_kernel, cudaFuncAttributeMaxDynamicSharedMemorySize,
                         (int)attn_smem);

    qkv_prep<<<QKV_BLOCKS + 514, 256>>>(node_features, in_proj_w, in_proj_b,
                                        W2, b2, out_w, out_b, proj_w, proj_b);
    attn_kernel<<<S_SCENES, 512, attn_smem>>>(positions, W1, b1,
                                              node_features, proj_w, out);
}